// round 14
// baseline (speedup 1.0000x reference)
#include <cuda_runtime.h>
#include <cuda_fp16.h>
#include <cstdint>

// ---------------------------------------------------------------------------
// ShiftedWindowMSA (B=32, 56x56, EMB=256, 8 heads, 7x7 windows) — fp16 e2e
//  permute_w1: w1 -> g_w1phT [768][256] fp16 K-major, (head,which,e) order
//  build_bias: bias+mask table, 4 window classes x 64 rows x 56 cols
//  qkv_gemm:   fp16 m16n8k16, 4 warps / 64x64 warp tiles, BK=32, 3-stage
//              cp.async; A staged as RAW f32 and converted to fp16 in
//              registers (kills the cvt_x kernel + its DRAM round-trip).
//              Epilogue scatters via roll(-4)+window: Q/K as [ws][32],
//              V TRANSPOSED as [e][56].
//  attn:       fp16 m16n8k16 attention, table softmax, zero-shuffle P
//              relayout, V^T smem rows 72 wide (K padded to 64), inverse
//              roll(+3) fp32 output.
// ---------------------------------------------------------------------------

#define WSZ 49
#define CHUNK 1792                    // halves per (window) chunk
#define ROWSTRIDE (64 * CHUNK)        // per (b,g): 64 windows

__device__ __half g_scr[(size_t)32 * 24 * ROWSTRIDE];
__device__ __half g_w1phT[768 * 256];
__device__ float  g_b1p[768];
__device__ float  g_bias[4 * 64 * 56];

__device__ __forceinline__ uint32_t packh2(float lo, float hi) {
    __half2 h = __floats2half2_rn(lo, hi);
    return *reinterpret_cast<uint32_t*>(&h);
}

__device__ __forceinline__ void mma_f16(float c[4], uint32_t a0, uint32_t a1,
                                        uint32_t a2, uint32_t a3,
                                        uint32_t b0, uint32_t b1) {
    asm volatile(
        "mma.sync.aligned.m16n8k16.row.col.f32.f16.f16.f32 "
        "{%0,%1,%2,%3}, {%4,%5,%6,%7}, {%8,%9}, {%0,%1,%2,%3};"
        : "+f"(c[0]), "+f"(c[1]), "+f"(c[2]), "+f"(c[3])
        : "r"(a0), "r"(a1), "r"(a2), "r"(a3), "r"(b0), "r"(b1));
}

// ---------------------------------------------------------------------------
__global__ void permute_w1_kernel(const float* __restrict__ w1,
                                  const float* __restrict__ b1) {
    int idx = blockIdx.x * blockDim.x + threadIdx.x;
    if (idx < 768 * 256) {
        int jn = idx >> 8, k = idx & 255;
        int g = jn >> 5, e = jn & 31;
        g_w1phT[idx] = __float2half_rn(w1[k * 768 + e * 24 + g]);
    }
    if (idx < 768) {
        int g = idx >> 5, e = idx & 31;
        g_b1p[idx] = b1[e * 24 + g];
    }
}

__global__ void build_bias_kernel(const float* __restrict__ pos) {
    int idx = blockIdx.x * blockDim.x + threadIdx.x;
    if (idx >= 4 * 64 * 56) return;
    int m = idx / 3584;
    int rem = idx - m * 3584;
    int row = rem / 56, cc = rem - (rem / 56) * 56;
    bool mu = (m >> 1), mv = (m & 1);
    int crow = row < 49 ? row : 48;
    int qt = crow / 7, ii = crow - qt * 7;
    float val = __int_as_float(0xff800000u);
    if (cc < 49) {
        int kt = cc / 7, jj = cc - kt * 7;
        val = pos[(kt - qt + 6) * 13 + (jj - ii + 6)];
        if (mu && ((qt >= 4) != (kt >= 4))) val = __int_as_float(0xff800000u);
        if (mv && ((ii >= 4) != (jj >= 4))) val = __int_as_float(0xff800000u);
    }
    g_bias[idx] = val;
}

// ---------------------------------------------------------------------------
// Stage 2: fp16 QKV GEMM, A from raw f32. Block 128x128, 4 warps (64x64),
//   BK=32, 3-stage cp.async.
// ---------------------------------------------------------------------------
#define ASTRF 36                          // f32 words per A smem row
#define BSTRH 40                          // halves per B smem row
#define A_STAGE_BYTES (128 * ASTRF * 4)   // 18432
#define B_STAGE_BYTES (128 * BSTRH * 2)   // 10240
#define STAGE_BYTES (A_STAGE_BYTES + B_STAGE_BYTES)   // 28672
#define GEMM_SMEM_BYTES (3 * STAGE_BYTES)             // 86016

__global__ __launch_bounds__(128, 2) void qkv_gemm_kernel(const float* __restrict__ x) {
    extern __shared__ char smraw[];

    const int tid  = threadIdx.x;
    const int warp = tid >> 5, lane = tid & 31;
    const int tg = lane >> 2, t4 = lane & 3;
    const int wm0 = (warp >> 1) * 64;
    const int wn0 = (warp & 1) * 64;
    const int tile_m = blockIdx.y * 128;
    const int tile_n = blockIdx.x * 128;

    auto load_stage = [&](int kc, int s) {
        float* As = reinterpret_cast<float*>(smraw + s * STAGE_BYTES);
        __half* Bs = reinterpret_cast<__half*>(smraw + s * STAGE_BYTES + A_STAGE_BYTES);
        // A: 128 rows x 8 16B-units (f32) = 1024 tasks, 8/thread
#pragma unroll
        for (int j = 0; j < 8; ++j) {
            int f = tid + j * 128;
            int row = f >> 3, u4 = (f & 7) * 4;
            uint32_t sa = (uint32_t)__cvta_generic_to_shared(&As[row * ASTRF + u4]);
            asm volatile("cp.async.cg.shared.global [%0], [%1], 16;"
                :: "r"(sa),
                   "l"(x + (size_t)(tile_m + row) * 256 + kc * 32 + u4));
        }
        // B: 128 rows x 4 16B-units (fp16) = 512 tasks, 4/thread
#pragma unroll
        for (int j = 0; j < 4; ++j) {
            int f = tid + j * 128;
            int row = f >> 2, u8 = (f & 3) * 8;
            uint32_t sa = (uint32_t)__cvta_generic_to_shared(&Bs[row * BSTRH + u8]);
            asm volatile("cp.async.cg.shared.global [%0], [%1], 16;"
                :: "r"(sa),
                   "l"(g_w1phT + (size_t)(tile_n + row) * 256 + kc * 32 + u8));
        }
        asm volatile("cp.async.commit_group;");
    };

    float c[4][8][4];
#pragma unroll
    for (int a = 0; a < 4; ++a)
#pragma unroll
        for (int b = 0; b < 8; ++b)
#pragma unroll
            for (int d = 0; d < 4; ++d) c[a][b][d] = 0.f;

    load_stage(0, 0);
    load_stage(1, 1);

#pragma unroll 1
    for (int kc = 0; kc < 8; ++kc) {
        if (kc < 7) asm volatile("cp.async.wait_group 1;");
        else        asm volatile("cp.async.wait_group 0;");
        __syncthreads();
        if (kc + 2 < 8) load_stage(kc + 2, (kc + 2) % 3);

        const float* aa = reinterpret_cast<const float*>(smraw + (kc % 3) * STAGE_BYTES);
        const __half* bb = reinterpret_cast<const __half*>(
            smraw + (kc % 3) * STAGE_BYTES + A_STAGE_BYTES);
#pragma unroll
        for (int kk = 0; kk < 32; kk += 16) {
            uint32_t a[4][4];
#pragma unroll
            for (int mt = 0; mt < 4; ++mt) {
                int r = wm0 + mt * 16 + tg;
                float2 f0 = *reinterpret_cast<const float2*>(&aa[r * ASTRF + kk + 2 * t4]);
                float2 f1 = *reinterpret_cast<const float2*>(&aa[(r + 8) * ASTRF + kk + 2 * t4]);
                float2 f2 = *reinterpret_cast<const float2*>(&aa[r * ASTRF + kk + 2 * t4 + 8]);
                float2 f3 = *reinterpret_cast<const float2*>(&aa[(r + 8) * ASTRF + kk + 2 * t4 + 8]);
                a[mt][0] = packh2(f0.x, f0.y);
                a[mt][1] = packh2(f1.x, f1.y);
                a[mt][2] = packh2(f2.x, f2.y);
                a[mt][3] = packh2(f3.x, f3.y);
            }
#pragma unroll
            for (int nt = 0; nt < 8; ++nt) {
                int n = wn0 + nt * 8 + tg;
                uint32_t b0 = *reinterpret_cast<const uint32_t*>(&bb[n * BSTRH + kk + 2 * t4]);
                uint32_t b1 = *reinterpret_cast<const uint32_t*>(&bb[n * BSTRH + kk + 2 * t4 + 8]);
#pragma unroll
                for (int mt = 0; mt < 4; ++mt)
                    mma_f16(c[mt][nt], a[mt][0], a[mt][1], a[mt][2], a[mt][3],
                            b0, b1);
            }
        }
    }

    // ---- epilogue: roll(-4)+window mapping per output row ----
    size_t qkbase[8];   // winoff + wr*32   (Q/K layout [ws][32])
    size_t voff[8];     // winoff + wr      (V^T layout [e][56])
#pragma unroll
    for (int mt = 0; mt < 4; ++mt) {
#pragma unroll
        for (int h = 0; h < 2; ++h) {
            int n = tile_m + wm0 + mt * 16 + tg + h * 8;
            int b = n / 3136;
            int r = n - b * 3136;
            int y = r / 56, xx = r - y * 56;
            int yr = (y + 52) % 56;
            int xr = (xx + 52) % 56;
            int u = yr / 7, wxr = yr - u * 7;
            int v = xr / 7, wyr = xr - v * 7;
            size_t winoff = (size_t)(b * 24) * ROWSTRIDE
                          + (size_t)(u * 8 + v) * CHUNK;
            int wr = wxr * 7 + wyr;
            qkbase[mt * 2 + h] = winoff + (size_t)wr * 32;
            voff[mt * 2 + h]   = winoff + (size_t)wr;
        }
    }
#pragma unroll
    for (int nt = 0; nt < 8; ++nt) {
        int jn0 = tile_n + wn0 + nt * 8 + t4 * 2;
        int g0 = jn0 >> 5;
        int which = g0 % 3;
        int e0 = jn0 & 31;
        float bias0 = g_b1p[jn0];
        float bias1 = g_b1p[jn0 + 1];
        size_t gRS = (size_t)g0 * ROWSTRIDE;
        if (which != 2) {
            size_t coff = gRS + e0;
#pragma unroll
            for (int mt = 0; mt < 4; ++mt) {
                *reinterpret_cast<uint32_t*>(&g_scr[qkbase[mt * 2 + 0] + coff]) =
                    packh2(c[mt][nt][0] + bias0, c[mt][nt][1] + bias1);
                *reinterpret_cast<uint32_t*>(&g_scr[qkbase[mt * 2 + 1] + coff]) =
                    packh2(c[mt][nt][2] + bias0, c[mt][nt][3] + bias1);
            }
        } else {
            // V stored transposed: g_scr[gRS + winoff + e*56 + wr]
#pragma unroll
            for (int mt = 0; mt < 4; ++mt) {
#pragma unroll
                for (int h = 0; h < 2; ++h) {
                    size_t vb = gRS + voff[mt * 2 + h];
                    g_scr[vb + (size_t)e0 * 56] =
                        __float2half_rn(c[mt][nt][h * 2 + 0] + bias0);
                    g_scr[vb + (size_t)(e0 + 1) * 56] =
                        __float2half_rn(c[mt][nt][h * 2 + 1] + bias1);
                }
            }
        }
    }
}

// ---------------------------------------------------------------------------
// Stage 3: fp16 attention. 128 threads per (b, head, window), 6 CTAs/SM.
//   V arrives pre-transposed [e][56]; smem rows widened to 72 (K padded to 64,
//   k=49..63 zeroed) so the g=3 B-fragment (k=48..63) stays in-row.
// ---------------------------------------------------------------------------
#define QSTR 40   // halves; frag banks (20*row + t4) % 32 -> conflict-free
#define VT   72   // V^T smem stride; frag banks (4*tg + t4 + 8g) -> conflict-free

__global__ __launch_bounds__(128, 6) void attn_kernel(float* __restrict__ out) {
    __shared__ __half sq[64 * QSTR];
    __shared__ __half sk[56 * QSTR];
    __shared__ __half svT[32 * VT];

    const int tid = threadIdx.x;
    const int warp = tid >> 5, lane = tid & 31;
    const int tg = lane >> 2, t4 = lane & 3;
    const int bid = blockIdx.x;
    const int b    = bid >> 9;
    const int head = (bid >> 6) & 7;
    const int win  = bid & 63;
    const int u = win >> 3, v = win & 7;
    const int mclass = ((u == 7) ? 2 : 0) + ((v == 7) ? 1 : 0);
    const float* tbl = g_bias + mclass * 3584;

    const __half* base = g_scr + (size_t)(b * 24 + head * 3) * ROWSTRIDE
                               + (size_t)win * CHUNK;

    // q,k: 49 rows x 4 16B-units = 196 tasks each
#pragma unroll
    for (int which = 0; which < 2; ++which) {
        const __half* src = base + (size_t)which * ROWSTRIDE;
        __half* dst = which ? sk : sq;
#pragma unroll
        for (int i = 0; i < 2; ++i) {
            int t = tid + i * 128;
            if (t < 196) {
                int row = t >> 2, o8 = (t & 3) * 8;
                *reinterpret_cast<uint4*>(&dst[row * QSTR + o8]) =
                    *reinterpret_cast<const uint4*>(src + row * 32 + o8);
            }
        }
    }
    // v^T: 32 rows x 8 16B-units into stride-72 rows.
    //   unit 0..5: copy k=0..47;  unit 6: {V[48], 0 x7};  unit 7: zeros.
    {
        const __half* vsrc = base + 2 * (size_t)ROWSTRIDE;
#pragma unroll
        for (int i = 0; i < 2; ++i) {
            int t = tid + i * 128;   // 256 tasks
            int row = t >> 3, uu = t & 7;
            uint4 val;
            if (uu < 6) {
                val = *reinterpret_cast<const uint4*>(vsrc + row * 56 + uu * 8);
            } else if (uu == 6) {
                val.x = (uint32_t)__half_as_ushort(vsrc[row * 56 + 48]);
                val.y = 0; val.z = 0; val.w = 0;
            } else {
                val.x = 0; val.y = 0; val.z = 0; val.w = 0;
            }
            *reinterpret_cast<uint4*>(&svT[row * VT + uu * 8]) = val;
        }
    }
    // zero q/k pad rows
    for (int t = tid; t < 15 * QSTR; t += 128) sq[49 * QSTR + t] = __ushort_as_half(0);
    for (int t = tid; t < 7 * QSTR; t += 128)  sk[49 * QSTR + t] = __ushort_as_half(0);
    __syncthreads();

    const int r0 = warp * 16 + tg;

    // ---- S = q k^T : cS[8][4], group 7 stays zero (P pad cols) ----
    float cS[8][4];
#pragma unroll
    for (int nt = 0; nt < 8; ++nt)
#pragma unroll
        for (int d = 0; d < 4; ++d) cS[nt][d] = 0.f;
#pragma unroll
    for (int kk = 0; kk < 32; kk += 16) {
        uint32_t a0 = *reinterpret_cast<const uint32_t*>(&sq[r0 * QSTR + kk + 2 * t4]);
        uint32_t a1 = *reinterpret_cast<const uint32_t*>(&sq[(r0 + 8) * QSTR + kk + 2 * t4]);
        uint32_t a2 = *reinterpret_cast<const uint32_t*>(&sq[r0 * QSTR + kk + 2 * t4 + 8]);
        uint32_t a3 = *reinterpret_cast<const uint32_t*>(&sq[(r0 + 8) * QSTR + kk + 2 * t4 + 8]);
#pragma unroll
        for (int nt = 0; nt < 7; ++nt) {
            int n = nt * 8 + tg;
            uint32_t b0 = *reinterpret_cast<const uint32_t*>(&sk[n * QSTR + kk + 2 * t4]);
            uint32_t b1 = *reinterpret_cast<const uint32_t*>(&sk[n * QSTR + kk + 2 * t4 + 8]);
            mma_f16(cS[nt], a0, a1, a2, a3, b0, b1);
        }
    }

    // ---- table-driven scale+bias+mask, in-register softmax ----
    const float SCALE = 0.17677669529663687f;   // 1/sqrt(32)
    const float NEG_INF = __int_as_float(0xff800000u);
#pragma unroll
    for (int r2 = 0; r2 < 2; ++r2) {
        int row = r0 + r2 * 8;
        const float* trow = tbl + row * 56 + 2 * t4;

        float mx = NEG_INF;
#pragma unroll
        for (int nt = 0; nt < 7; ++nt) {
            float2 bv = *reinterpret_cast<const float2*>(trow + nt * 8);
            float v0 = fmaf(cS[nt][r2 * 2 + 0], SCALE, bv.x);
            float v1 = fmaf(cS[nt][r2 * 2 + 1], SCALE, bv.y);
            cS[nt][r2 * 2 + 0] = v0;
            cS[nt][r2 * 2 + 1] = v1;
            mx = fmaxf(mx, fmaxf(v0, v1));
        }
        mx = fmaxf(mx, __shfl_xor_sync(0xffffffffu, mx, 1));
        mx = fmaxf(mx, __shfl_xor_sync(0xffffffffu, mx, 2));
        float sum = 0.f;
#pragma unroll
        for (int nt = 0; nt < 7; ++nt) {
#pragma unroll
            for (int d = 0; d < 2; ++d) {
                float e = __expf(cS[nt][r2 * 2 + d] - mx);
                cS[nt][r2 * 2 + d] = e;
                sum += e;
            }
        }
        sum += __shfl_xor_sync(0xffffffffu, sum, 1);
        sum += __shfl_xor_sync(0xffffffffu, sum, 2);
        float inv = 1.f / sum;
#pragma unroll
        for (int nt = 0; nt < 7; ++nt) {
            cS[nt][r2 * 2 + 0] *= inv;
            cS[nt][r2 * 2 + 1] *= inv;
        }
    }

    // ---- O = P v : P C-frag pairs pack directly into fp16 A-frags ----
    float cO[4][4];
#pragma unroll
    for (int nt = 0; nt < 4; ++nt)
#pragma unroll
        for (int d = 0; d < 4; ++d) cO[nt][d] = 0.f;

#pragma unroll
    for (int g = 0; g < 4; ++g) {
        uint32_t a0 = packh2(cS[2 * g][0], cS[2 * g][1]);
        uint32_t a1 = packh2(cS[2 * g][2], cS[2 * g][3]);
        uint32_t a2 = packh2(cS[2 * g + 1][0], cS[2 * g + 1][1]);
        uint32_t a3 = packh2(cS[2 * g + 1][2], cS[2 * g + 1][3]);
#pragma unroll
        for (int nt = 0; nt < 4; ++nt) {
            int n = nt * 8 + tg;
            uint32_t b0 = *reinterpret_cast<const uint32_t*>(&svT[n * VT + 16 * g + 2 * t4]);
            uint32_t b1 = *reinterpret_cast<const uint32_t*>(&svT[n * VT + 16 * g + 2 * t4 + 8]);
            mma_f16(cO[nt], a0, a1, a2, a3, b0, b1);
        }
    }

    // ---- store with inverse roll(+3); channel = e*8 + head ----
#pragma unroll
    for (int r2 = 0; r2 < 2; ++r2) {
        int row = r0 + r2 * 8;
        if (row < 49) {
            int qt = (row * 9363) >> 16;
            int ii = row - qt * 7;
            int yo = u * 7 + qt + 3; if (yo >= 56) yo -= 56;
            int xo = v * 7 + ii + 3; if (xo >= 56) xo -= 56;
            float* op = out + ((size_t)((b * 56 + yo) * 56 + xo)) * 256 + head;
#pragma unroll
            for (int nt = 0; nt < 4; ++nt) {
                int e0 = nt * 8 + 2 * t4;
                op[(size_t)e0 * 8]       = cO[nt][r2 * 2 + 0];
                op[(size_t)(e0 + 1) * 8] = cO[nt][r2 * 2 + 1];
            }
        }
    }
}

// ---------------------------------------------------------------------------
extern "C" void kernel_launch(void* const* d_in, const int* in_sizes, int n_in,
                              void* d_out, int out_size) {
    const float* x   = (const float*)d_in[0];
    const float* w1  = (const float*)d_in[1];
    const float* b1  = (const float*)d_in[2];
    const float* pos = (const float*)d_in[3];
    float* out = (float*)d_out;

    static int configured = 0;
    if (!configured) {
        cudaFuncSetAttribute(qkv_gemm_kernel,
                             cudaFuncAttributeMaxDynamicSharedMemorySize,
                             GEMM_SMEM_BYTES);
        configured = 1;
    }

    permute_w1_kernel<<<768, 256>>>(w1, b1);
    build_bias_kernel<<<56, 256>>>(pos);
    qkv_gemm_kernel<<<dim3(6, 784), 128, GEMM_SMEM_BYTES>>>(x);
    attn_kernel<<<16384, 128>>>(out);
}

// round 15
// speedup vs baseline: 1.0325x; 1.0325x over previous
#include <cuda_runtime.h>
#include <cuda_fp16.h>
#include <cstdint>

// ---------------------------------------------------------------------------
// ShiftedWindowMSA (B=32, 56x56, EMB=256, 8 heads, 7x7 windows) — fp16 e2e
//  cvt_x:      x -> fp16 g_xh (precompute; keeps GEMM LDS->mma path minimal)
//  permute_w1: w1 -> g_w1phT [768][256] fp16 K-major, (head,which,e) order
//  build_bias: bias+mask table, 4 window classes x 64 rows x 56 cols
//  qkv_gemm:   fp16 m16n8k16, 128 thr / 4 warps / 64x64 warp tiles, BK=32,
//              3-stage cp.async (r9 champion geometry). Epilogue scatters via
//              roll(-4)+window: Q/K as [ws][32] fp16, V TRANSPOSED as [e][56].
//  attn:       fp16 m16n8k16 attention (r14 verbatim, 146.9us measured).
// ---------------------------------------------------------------------------

#define WSZ 49
#define CHUNK 1792                    // halves per (window) chunk
#define ROWSTRIDE (64 * CHUNK)        // per (b,g): 64 windows

__device__ __half g_scr[(size_t)32 * 24 * ROWSTRIDE];
__device__ __half g_xh[(size_t)32 * 3136 * 256];
__device__ __half g_w1phT[768 * 256];
__device__ float  g_b1p[768];
__device__ float  g_bias[4 * 64 * 56];

__device__ __forceinline__ uint32_t packh2(float lo, float hi) {
    __half2 h = __floats2half2_rn(lo, hi);
    return *reinterpret_cast<uint32_t*>(&h);
}

__device__ __forceinline__ void mma_f16(float c[4], uint32_t a0, uint32_t a1,
                                        uint32_t a2, uint32_t a3,
                                        uint32_t b0, uint32_t b1) {
    asm volatile(
        "mma.sync.aligned.m16n8k16.row.col.f32.f16.f16.f32 "
        "{%0,%1,%2,%3}, {%4,%5,%6,%7}, {%8,%9}, {%0,%1,%2,%3};"
        : "+f"(c[0]), "+f"(c[1]), "+f"(c[2]), "+f"(c[3])
        : "r"(a0), "r"(a1), "r"(a2), "r"(a3), "r"(b0), "r"(b1));
}

// ---------------------------------------------------------------------------
__global__ __launch_bounds__(256) void cvt_x_kernel(const float* __restrict__ x) {
    size_t base = (size_t)blockIdx.x * 1024 + threadIdx.x;
#pragma unroll
    for (int i = 0; i < 4; ++i) {
        size_t g = base + (size_t)i * 256;
        float4 v0 = reinterpret_cast<const float4*>(x)[g * 2];
        float4 v1 = reinterpret_cast<const float4*>(x)[g * 2 + 1];
        uint4 o;
        o.x = packh2(v0.x, v0.y);
        o.y = packh2(v0.z, v0.w);
        o.z = packh2(v1.x, v1.y);
        o.w = packh2(v1.z, v1.w);
        reinterpret_cast<uint4*>(g_xh)[g] = o;
    }
}

__global__ void permute_w1_kernel(const float* __restrict__ w1,
                                  const float* __restrict__ b1) {
    int idx = blockIdx.x * blockDim.x + threadIdx.x;
    if (idx < 768 * 256) {
        int jn = idx >> 8, k = idx & 255;
        int g = jn >> 5, e = jn & 31;
        g_w1phT[idx] = __float2half_rn(w1[k * 768 + e * 24 + g]);
    }
    if (idx < 768) {
        int g = idx >> 5, e = idx & 31;
        g_b1p[idx] = b1[e * 24 + g];
    }
}

__global__ void build_bias_kernel(const float* __restrict__ pos) {
    int idx = blockIdx.x * blockDim.x + threadIdx.x;
    if (idx >= 4 * 64 * 56) return;
    int m = idx / 3584;
    int rem = idx - m * 3584;
    int row = rem / 56, cc = rem - (rem / 56) * 56;
    bool mu = (m >> 1), mv = (m & 1);
    int crow = row < 49 ? row : 48;
    int qt = crow / 7, ii = crow - qt * 7;
    float val = __int_as_float(0xff800000u);
    if (cc < 49) {
        int kt = cc / 7, jj = cc - kt * 7;
        val = pos[(kt - qt + 6) * 13 + (jj - ii + 6)];
        if (mu && ((qt >= 4) != (kt >= 4))) val = __int_as_float(0xff800000u);
        if (mv && ((ii >= 4) != (jj >= 4))) val = __int_as_float(0xff800000u);
    }
    g_bias[idx] = val;
}

// ---------------------------------------------------------------------------
// Stage 2: fp16 QKV GEMM. Block 128x128, 4 warps, warp tile 64x64, BK=32,
//   3-stage cp.async. A,B K-major [128 rows][32 halves], row stride 40 halves.
// ---------------------------------------------------------------------------
#define HSTR 40                          // halves per smem row (80 B)
#define STAGE_HALVES (2 * 128 * HSTR)    // A + B per stage
#define GEMM_SMEM_BYTES (3 * STAGE_HALVES * 2)   // 61440

__global__ __launch_bounds__(128, 2) void qkv_gemm_kernel() {
    extern __shared__ __half smh[];

    const int tid  = threadIdx.x;
    const int warp = tid >> 5, lane = tid & 31;
    const int tg = lane >> 2, t4 = lane & 3;
    const int wm0 = (warp >> 1) * 64;
    const int wn0 = (warp & 1) * 64;
    const int tile_m = blockIdx.y * 128;
    const int tile_n = blockIdx.x * 128;

    const int lrow = tid >> 2;          // 0..31, rows advance by 32 per j
    const int lunit = (tid & 3) * 8;    // halves offset within row

    auto load_stage = [&](int kc, int s) {
        __half* As = smh + s * STAGE_HALVES;
        __half* Bs = As + 128 * HSTR;
        const __half* asrc = g_xh + (size_t)(tile_m + lrow) * 256 + kc * 32 + lunit;
        const __half* bsrc = g_w1phT + (size_t)(tile_n + lrow) * 256 + kc * 32 + lunit;
#pragma unroll
        for (int j = 0; j < 4; ++j) {
            uint32_t sa = (uint32_t)__cvta_generic_to_shared(
                &As[(lrow + j * 32) * HSTR + lunit]);
            asm volatile("cp.async.cg.shared.global [%0], [%1], 16;"
                         :: "r"(sa), "l"(asrc + (size_t)j * 32 * 256));
        }
#pragma unroll
        for (int j = 0; j < 4; ++j) {
            uint32_t sa = (uint32_t)__cvta_generic_to_shared(
                &Bs[(lrow + j * 32) * HSTR + lunit]);
            asm volatile("cp.async.cg.shared.global [%0], [%1], 16;"
                         :: "r"(sa), "l"(bsrc + (size_t)j * 32 * 256));
        }
        asm volatile("cp.async.commit_group;");
    };

    float c[4][8][4];
#pragma unroll
    for (int a = 0; a < 4; ++a)
#pragma unroll
        for (int b = 0; b < 8; ++b)
#pragma unroll
            for (int d = 0; d < 4; ++d) c[a][b][d] = 0.f;

    load_stage(0, 0);
    load_stage(1, 1);

#pragma unroll 1
    for (int kc = 0; kc < 8; ++kc) {
        if (kc < 7) asm volatile("cp.async.wait_group 1;");
        else        asm volatile("cp.async.wait_group 0;");
        __syncthreads();
        if (kc + 2 < 8) load_stage(kc + 2, (kc + 2) % 3);

        const __half* aa = smh + (kc % 3) * STAGE_HALVES;
        const __half* bb = aa + 128 * HSTR;
#pragma unroll
        for (int kk = 0; kk < 32; kk += 16) {
            uint32_t a[4][4];
#pragma unroll
            for (int mt = 0; mt < 4; ++mt) {
                int r = wm0 + mt * 16 + tg;
                a[mt][0] = *reinterpret_cast<const uint32_t*>(&aa[r * HSTR + kk + 2 * t4]);
                a[mt][1] = *reinterpret_cast<const uint32_t*>(&aa[(r + 8) * HSTR + kk + 2 * t4]);
                a[mt][2] = *reinterpret_cast<const uint32_t*>(&aa[r * HSTR + kk + 2 * t4 + 8]);
                a[mt][3] = *reinterpret_cast<const uint32_t*>(&aa[(r + 8) * HSTR + kk + 2 * t4 + 8]);
            }
#pragma unroll
            for (int nt = 0; nt < 8; ++nt) {
                int n = wn0 + nt * 8 + tg;
                uint32_t b0 = *reinterpret_cast<const uint32_t*>(&bb[n * HSTR + kk + 2 * t4]);
                uint32_t b1 = *reinterpret_cast<const uint32_t*>(&bb[n * HSTR + kk + 2 * t4 + 8]);
#pragma unroll
                for (int mt = 0; mt < 4; ++mt)
                    mma_f16(c[mt][nt], a[mt][0], a[mt][1], a[mt][2], a[mt][3],
                            b0, b1);
            }
        }
    }

    // ---- epilogue: roll(-4)+window mapping per output row ----
    size_t qkbase[8];   // winoff + wr*32   (Q/K layout [ws][32])
    size_t voff[8];     // winoff + wr      (V^T layout [e][56])
#pragma unroll
    for (int mt = 0; mt < 4; ++mt) {
#pragma unroll
        for (int h = 0; h < 2; ++h) {
            int n = tile_m + wm0 + mt * 16 + tg + h * 8;
            int b = n / 3136;
            int r = n - b * 3136;
            int y = r / 56, xx = r - y * 56;
            int yr = (y + 52) % 56;
            int xr = (xx + 52) % 56;
            int u = yr / 7, wxr = yr - u * 7;
            int v = xr / 7, wyr = xr - v * 7;
            size_t winoff = (size_t)(b * 24) * ROWSTRIDE
                          + (size_t)(u * 8 + v) * CHUNK;
            int wr = wxr * 7 + wyr;
            qkbase[mt * 2 + h] = winoff + (size_t)wr * 32;
            voff[mt * 2 + h]   = winoff + (size_t)wr;
        }
    }
#pragma unroll
    for (int nt = 0; nt < 8; ++nt) {
        int jn0 = tile_n + wn0 + nt * 8 + t4 * 2;
        int g0 = jn0 >> 5;
        int which = g0 % 3;
        int e0 = jn0 & 31;
        float bias0 = g_b1p[jn0];
        float bias1 = g_b1p[jn0 + 1];
        size_t gRS = (size_t)g0 * ROWSTRIDE;
        if (which != 2) {
            size_t coff = gRS + e0;
#pragma unroll
            for (int mt = 0; mt < 4; ++mt) {
                *reinterpret_cast<uint32_t*>(&g_scr[qkbase[mt * 2 + 0] + coff]) =
                    packh2(c[mt][nt][0] + bias0, c[mt][nt][1] + bias1);
                *reinterpret_cast<uint32_t*>(&g_scr[qkbase[mt * 2 + 1] + coff]) =
                    packh2(c[mt][nt][2] + bias0, c[mt][nt][3] + bias1);
            }
        } else {
            // V stored transposed: g_scr[gRS + winoff + e*56 + wr]
#pragma unroll
            for (int mt = 0; mt < 4; ++mt) {
#pragma unroll
                for (int h = 0; h < 2; ++h) {
                    size_t vb = gRS + voff[mt * 2 + h];
                    g_scr[vb + (size_t)e0 * 56] =
                        __float2half_rn(c[mt][nt][h * 2 + 0] + bias0);
                    g_scr[vb + (size_t)(e0 + 1) * 56] =
                        __float2half_rn(c[mt][nt][h * 2 + 1] + bias1);
                }
            }
        }
    }
}

// ---------------------------------------------------------------------------
// Stage 3: fp16 attention (r14 verbatim). 128 threads per (b, head, window).
// ---------------------------------------------------------------------------
#define QSTR 40   // halves; frag banks (20*row + t4) % 32 -> conflict-free
#define VT   72   // V^T smem stride; frag banks (4*tg + t4 + 8g) -> conflict-free

__global__ __launch_bounds__(128, 6) void attn_kernel(float* __restrict__ out) {
    __shared__ __half sq[64 * QSTR];
    __shared__ __half sk[56 * QSTR];
    __shared__ __half svT[32 * VT];

    const int tid = threadIdx.x;
    const int warp = tid >> 5, lane = tid & 31;
    const int tg = lane >> 2, t4 = lane & 3;
    const int bid = blockIdx.x;
    const int b    = bid >> 9;
    const int head = (bid >> 6) & 7;
    const int win  = bid & 63;
    const int u = win >> 3, v = win & 7;
    const int mclass = ((u == 7) ? 2 : 0) + ((v == 7) ? 1 : 0);
    const float* tbl = g_bias + mclass * 3584;

    const __half* base = g_scr + (size_t)(b * 24 + head * 3) * ROWSTRIDE
                               + (size_t)win * CHUNK;

    // q,k: 49 rows x 4 16B-units = 196 tasks each
#pragma unroll
    for (int which = 0; which < 2; ++which) {
        const __half* src = base + (size_t)which * ROWSTRIDE;
        __half* dst = which ? sk : sq;
#pragma unroll
        for (int i = 0; i < 2; ++i) {
            int t = tid + i * 128;
            if (t < 196) {
                int row = t >> 2, o8 = (t & 3) * 8;
                *reinterpret_cast<uint4*>(&dst[row * QSTR + o8]) =
                    *reinterpret_cast<const uint4*>(src + row * 32 + o8);
            }
        }
    }
    // v^T: 32 rows x 8 16B-units into stride-72 rows.
    //   unit 0..5: copy k=0..47;  unit 6: {V[48], 0 x7};  unit 7: zeros.
    {
        const __half* vsrc = base + 2 * (size_t)ROWSTRIDE;
#pragma unroll
        for (int i = 0; i < 2; ++i) {
            int t = tid + i * 128;   // 256 tasks
            int row = t >> 3, uu = t & 7;
            uint4 val;
            if (uu < 6) {
                val = *reinterpret_cast<const uint4*>(vsrc + row * 56 + uu * 8);
            } else if (uu == 6) {
                val.x = (uint32_t)__half_as_ushort(vsrc[row * 56 + 48]);
                val.y = 0; val.z = 0; val.w = 0;
            } else {
                val.x = 0; val.y = 0; val.z = 0; val.w = 0;
            }
            *reinterpret_cast<uint4*>(&svT[row * VT + uu * 8]) = val;
        }
    }
    // zero q/k pad rows
    for (int t = tid; t < 15 * QSTR; t += 128) sq[49 * QSTR + t] = __ushort_as_half(0);
    for (int t = tid; t < 7 * QSTR; t += 128)  sk[49 * QSTR + t] = __ushort_as_half(0);
    __syncthreads();

    const int r0 = warp * 16 + tg;

    // ---- S = q k^T : cS[8][4], group 7 stays zero (P pad cols) ----
    float cS[8][4];
#pragma unroll
    for (int nt = 0; nt < 8; ++nt)
#pragma unroll
        for (int d = 0; d < 4; ++d) cS[nt][d] = 0.f;
#pragma unroll
    for (int kk = 0; kk < 32; kk += 16) {
        uint32_t a0 = *reinterpret_cast<const uint32_t*>(&sq[r0 * QSTR + kk + 2 * t4]);
        uint32_t a1 = *reinterpret_cast<const uint32_t*>(&sq[(r0 + 8) * QSTR + kk + 2 * t4]);
        uint32_t a2 = *reinterpret_cast<const uint32_t*>(&sq[r0 * QSTR + kk + 2 * t4 + 8]);
        uint32_t a3 = *reinterpret_cast<const uint32_t*>(&sq[(r0 + 8) * QSTR + kk + 2 * t4 + 8]);
#pragma unroll
        for (int nt = 0; nt < 7; ++nt) {
            int n = nt * 8 + tg;
            uint32_t b0 = *reinterpret_cast<const uint32_t*>(&sk[n * QSTR + kk + 2 * t4]);
            uint32_t b1 = *reinterpret_cast<const uint32_t*>(&sk[n * QSTR + kk + 2 * t4 + 8]);
            mma_f16(cS[nt], a0, a1, a2, a3, b0, b1);
        }
    }

    // ---- table-driven scale+bias+mask, in-register softmax ----
    const float SCALE = 0.17677669529663687f;   // 1/sqrt(32)
    const float NEG_INF = __int_as_float(0xff800000u);
#pragma unroll
    for (int r2 = 0; r2 < 2; ++r2) {
        int row = r0 + r2 * 8;
        const float* trow = tbl + row * 56 + 2 * t4;

        float mx = NEG_INF;
#pragma unroll
        for (int nt = 0; nt < 7; ++nt) {
            float2 bv = *reinterpret_cast<const float2*>(trow + nt * 8);
            float v0 = fmaf(cS[nt][r2 * 2 + 0], SCALE, bv.x);
            float v1 = fmaf(cS[nt][r2 * 2 + 1], SCALE, bv.y);
            cS[nt][r2 * 2 + 0] = v0;
            cS[nt][r2 * 2 + 1] = v1;
            mx = fmaxf(mx, fmaxf(v0, v1));
        }
        mx = fmaxf(mx, __shfl_xor_sync(0xffffffffu, mx, 1));
        mx = fmaxf(mx, __shfl_xor_sync(0xffffffffu, mx, 2));
        float sum = 0.f;
#pragma unroll
        for (int nt = 0; nt < 7; ++nt) {
#pragma unroll
            for (int d = 0; d < 2; ++d) {
                float e = __expf(cS[nt][r2 * 2 + d] - mx);
                cS[nt][r2 * 2 + d] = e;
                sum += e;
            }
        }
        sum += __shfl_xor_sync(0xffffffffu, sum, 1);
        sum += __shfl_xor_sync(0xffffffffu, sum, 2);
        float inv = 1.f / sum;
#pragma unroll
        for (int nt = 0; nt < 7; ++nt) {
            cS[nt][r2 * 2 + 0] *= inv;
            cS[nt][r2 * 2 + 1] *= inv;
        }
    }

    // ---- O = P v : P C-frag pairs pack directly into fp16 A-frags ----
    float cO[4][4];
#pragma unroll
    for (int nt = 0; nt < 4; ++nt)
#pragma unroll
        for (int d = 0; d < 4; ++d) cO[nt][d] = 0.f;

#pragma unroll
    for (int g = 0; g < 4; ++g) {
        uint32_t a0 = packh2(cS[2 * g][0], cS[2 * g][1]);
        uint32_t a1 = packh2(cS[2 * g][2], cS[2 * g][3]);
        uint32_t a2 = packh2(cS[2 * g + 1][0], cS[2 * g + 1][1]);
        uint32_t a3 = packh2(cS[2 * g + 1][2], cS[2 * g + 1][3]);
#pragma unroll
        for (int nt = 0; nt < 4; ++nt) {
            int n = nt * 8 + tg;
            uint32_t b0 = *reinterpret_cast<const uint32_t*>(&svT[n * VT + 16 * g + 2 * t4]);
            uint32_t b1 = *reinterpret_cast<const uint32_t*>(&svT[n * VT + 16 * g + 2 * t4 + 8]);
            mma_f16(cO[nt], a0, a1, a2, a3, b0, b1);
        }
    }

    // ---- store with inverse roll(+3); channel = e*8 + head ----
#pragma unroll
    for (int r2 = 0; r2 < 2; ++r2) {
        int row = r0 + r2 * 8;
        if (row < 49) {
            int qt = (row * 9363) >> 16;
            int ii = row - qt * 7;
            int yo = u * 7 + qt + 3; if (yo >= 56) yo -= 56;
            int xo = v * 7 + ii + 3; if (xo >= 56) xo -= 56;
            float* op = out + ((size_t)((b * 56 + yo) * 56 + xo)) * 256 + head;
#pragma unroll
            for (int nt = 0; nt < 4; ++nt) {
                int e0 = nt * 8 + 2 * t4;
                op[(size_t)e0 * 8]       = cO[nt][r2 * 2 + 0];
                op[(size_t)(e0 + 1) * 8] = cO[nt][r2 * 2 + 1];
            }
        }
    }
}

// ---------------------------------------------------------------------------
extern "C" void kernel_launch(void* const* d_in, const int* in_sizes, int n_in,
                              void* d_out, int out_size) {
    const float* x   = (const float*)d_in[0];
    const float* w1  = (const float*)d_in[1];
    const float* b1  = (const float*)d_in[2];
    const float* pos = (const float*)d_in[3];
    float* out = (float*)d_out;

    static int configured = 0;
    if (!configured) {
        cudaFuncSetAttribute(qkv_gemm_kernel,
                             cudaFuncAttributeMaxDynamicSharedMemorySize,
                             GEMM_SMEM_BYTES);
        configured = 1;
    }

    cvt_x_kernel<<<3136, 256>>>(x);
    permute_w1_kernel<<<768, 256>>>(w1, b1);
    build_bias_kernel<<<56, 256>>>(pos);
    qkv_gemm_kernel<<<dim3(6, 784), 128, GEMM_SMEM_BYTES>>>();
    attn_kernel<<<16384, 128>>>(out);
}

// round 16
// speedup vs baseline: 1.1387x; 1.1028x over previous
#include <cuda_runtime.h>
#include <cuda_fp16.h>
#include <cstdint>

// ---------------------------------------------------------------------------
// ShiftedWindowMSA (B=32, 56x56, EMB=256, 8 heads, 7x7 windows) — fp16 e2e
//  cvt_x:      x -> fp16 g_xh
//  permute_w1: w1 -> g_w1phT [768][256] fp16 K-major, (head,which,e) order
//  build_bias: bias+mask table, 4 window classes x 64 rows x 56 cols
//  qkv_gemm:   fp16 m16n8k16, 128 thr / 4 warps / 64x64 warp tiles, BK=32,
//              3-stage cp.async (r9 measured-best config). Epilogue scatters
//              via roll(-4)+window: q/k/v all [ws][32] fp16, fully vectorized.
//  attn:       fp16 m16n8k16 attention; V B-fragments via ldmatrix.x4.trans
//              (hardware transpose — no V^T scratch, no scalar stores),
//              table softmax, zero-shuffle P relayout, roll(+3) fp32 output.
// ---------------------------------------------------------------------------

#define WSZ 49
#define ROWSTRIDE 100352   // 64 windows * 49 * 32 per (b,g)

__device__ __half g_scr[(size_t)32 * 24 * ROWSTRIDE];
__device__ __half g_xh[(size_t)32 * 3136 * 256];
__device__ __half g_w1phT[768 * 256];
__device__ float  g_b1p[768];
__device__ float  g_bias[4 * 64 * 56];

__device__ __forceinline__ uint32_t packh2(float lo, float hi) {
    __half2 h = __floats2half2_rn(lo, hi);
    return *reinterpret_cast<uint32_t*>(&h);
}

__device__ __forceinline__ void mma_f16(float c[4], uint32_t a0, uint32_t a1,
                                        uint32_t a2, uint32_t a3,
                                        uint32_t b0, uint32_t b1) {
    asm volatile(
        "mma.sync.aligned.m16n8k16.row.col.f32.f16.f16.f32 "
        "{%0,%1,%2,%3}, {%4,%5,%6,%7}, {%8,%9}, {%0,%1,%2,%3};"
        : "+f"(c[0]), "+f"(c[1]), "+f"(c[2]), "+f"(c[3])
        : "r"(a0), "r"(a1), "r"(a2), "r"(a3), "r"(b0), "r"(b1));
}

__device__ __forceinline__ void ldmx4t(uint32_t& r0, uint32_t& r1,
                                       uint32_t& r2, uint32_t& r3,
                                       uint32_t addr) {
    asm volatile(
        "ldmatrix.sync.aligned.m8n8.x4.trans.shared.b16 {%0,%1,%2,%3}, [%4];"
        : "=r"(r0), "=r"(r1), "=r"(r2), "=r"(r3) : "r"(addr));
}

// ---------------------------------------------------------------------------
__global__ __launch_bounds__(256) void cvt_x_kernel(const float* __restrict__ x) {
    size_t base = (size_t)blockIdx.x * 1024 + threadIdx.x;
#pragma unroll
    for (int i = 0; i < 4; ++i) {
        size_t g = base + (size_t)i * 256;
        float4 v0 = reinterpret_cast<const float4*>(x)[g * 2];
        float4 v1 = reinterpret_cast<const float4*>(x)[g * 2 + 1];
        uint4 o;
        o.x = packh2(v0.x, v0.y);
        o.y = packh2(v0.z, v0.w);
        o.z = packh2(v1.x, v1.y);
        o.w = packh2(v1.z, v1.w);
        reinterpret_cast<uint4*>(g_xh)[g] = o;
    }
}

__global__ void permute_w1_kernel(const float* __restrict__ w1,
                                  const float* __restrict__ b1) {
    int idx = blockIdx.x * blockDim.x + threadIdx.x;
    if (idx < 768 * 256) {
        int jn = idx >> 8, k = idx & 255;
        int g = jn >> 5, e = jn & 31;
        g_w1phT[idx] = __float2half_rn(w1[k * 768 + e * 24 + g]);
    }
    if (idx < 768) {
        int g = idx >> 5, e = idx & 31;
        g_b1p[idx] = b1[e * 24 + g];
    }
}

__global__ void build_bias_kernel(const float* __restrict__ pos) {
    int idx = blockIdx.x * blockDim.x + threadIdx.x;
    if (idx >= 4 * 64 * 56) return;
    int m = idx / 3584;
    int rem = idx - m * 3584;
    int row = rem / 56, cc = rem - (rem / 56) * 56;
    bool mu = (m >> 1), mv = (m & 1);
    int crow = row < 49 ? row : 48;
    int qt = crow / 7, ii = crow - qt * 7;
    float val = __int_as_float(0xff800000u);
    if (cc < 49) {
        int kt = cc / 7, jj = cc - kt * 7;
        val = pos[(kt - qt + 6) * 13 + (jj - ii + 6)];
        if (mu && ((qt >= 4) != (kt >= 4))) val = __int_as_float(0xff800000u);
        if (mv && ((ii >= 4) != (jj >= 4))) val = __int_as_float(0xff800000u);
    }
    g_bias[idx] = val;
}

// ---------------------------------------------------------------------------
// Stage 2: fp16 QKV GEMM (r9 config). Block 128x128, 4 warps, warp tile
//   64x64, BK=32, 3-stage cp.async; [ws][32] vectorized epilogue.
// ---------------------------------------------------------------------------
#define HSTR 40
#define STAGE_HALVES (2 * 128 * HSTR)
#define GEMM_SMEM_BYTES (3 * STAGE_HALVES * 2)

__global__ __launch_bounds__(128, 2) void qkv_gemm_kernel() {
    extern __shared__ __half smh[];

    const int tid  = threadIdx.x;
    const int warp = tid >> 5, lane = tid & 31;
    const int tg = lane >> 2, t4 = lane & 3;
    const int wm0 = (warp >> 1) * 64;
    const int wn0 = (warp & 1) * 64;
    const int tile_m = blockIdx.y * 128;
    const int tile_n = blockIdx.x * 128;

    const int lrow = tid >> 2;
    const int lunit = (tid & 3) * 8;

    auto load_stage = [&](int kc, int s) {
        __half* As = smh + s * STAGE_HALVES;
        __half* Bs = As + 128 * HSTR;
        const __half* asrc = g_xh + (size_t)(tile_m + lrow) * 256 + kc * 32 + lunit;
        const __half* bsrc = g_w1phT + (size_t)(tile_n + lrow) * 256 + kc * 32 + lunit;
#pragma unroll
        for (int j = 0; j < 4; ++j) {
            uint32_t sa = (uint32_t)__cvta_generic_to_shared(
                &As[(lrow + j * 32) * HSTR + lunit]);
            asm volatile("cp.async.cg.shared.global [%0], [%1], 16;"
                         :: "r"(sa), "l"(asrc + (size_t)j * 32 * 256));
        }
#pragma unroll
        for (int j = 0; j < 4; ++j) {
            uint32_t sa = (uint32_t)__cvta_generic_to_shared(
                &Bs[(lrow + j * 32) * HSTR + lunit]);
            asm volatile("cp.async.cg.shared.global [%0], [%1], 16;"
                         :: "r"(sa), "l"(bsrc + (size_t)j * 32 * 256));
        }
        asm volatile("cp.async.commit_group;");
    };

    float c[4][8][4];
#pragma unroll
    for (int a = 0; a < 4; ++a)
#pragma unroll
        for (int b = 0; b < 8; ++b)
#pragma unroll
            for (int d = 0; d < 4; ++d) c[a][b][d] = 0.f;

    load_stage(0, 0);
    load_stage(1, 1);

#pragma unroll 1
    for (int kc = 0; kc < 8; ++kc) {
        if (kc < 7) asm volatile("cp.async.wait_group 1;");
        else        asm volatile("cp.async.wait_group 0;");
        __syncthreads();
        if (kc + 2 < 8) load_stage(kc + 2, (kc + 2) % 3);

        const __half* aa = smh + (kc % 3) * STAGE_HALVES;
        const __half* bb = aa + 128 * HSTR;
#pragma unroll
        for (int kk = 0; kk < 32; kk += 16) {
            uint32_t a[4][4];
#pragma unroll
            for (int mt = 0; mt < 4; ++mt) {
                int r = wm0 + mt * 16 + tg;
                a[mt][0] = *reinterpret_cast<const uint32_t*>(&aa[r * HSTR + kk + 2 * t4]);
                a[mt][1] = *reinterpret_cast<const uint32_t*>(&aa[(r + 8) * HSTR + kk + 2 * t4]);
                a[mt][2] = *reinterpret_cast<const uint32_t*>(&aa[r * HSTR + kk + 2 * t4 + 8]);
                a[mt][3] = *reinterpret_cast<const uint32_t*>(&aa[(r + 8) * HSTR + kk + 2 * t4 + 8]);
            }
#pragma unroll
            for (int nt = 0; nt < 8; ++nt) {
                int n = wn0 + nt * 8 + tg;
                uint32_t b0 = *reinterpret_cast<const uint32_t*>(&bb[n * HSTR + kk + 2 * t4]);
                uint32_t b1 = *reinterpret_cast<const uint32_t*>(&bb[n * HSTR + kk + 2 * t4 + 8]);
#pragma unroll
                for (int mt = 0; mt < 4; ++mt)
                    mma_f16(c[mt][nt], a[mt][0], a[mt][1], a[mt][2], a[mt][3],
                            b0, b1);
            }
        }
    }

    // epilogue: scatter via roll(-4)+window partition; fp16(acc+bias)
    size_t rowbase[8];
#pragma unroll
    for (int mt = 0; mt < 4; ++mt) {
#pragma unroll
        for (int h = 0; h < 2; ++h) {
            int n = tile_m + wm0 + mt * 16 + tg + h * 8;
            int b = n / 3136;
            int r = n - b * 3136;
            int y = r / 56, xx = r - y * 56;
            int yr = (y + 52) % 56;
            int xr = (xx + 52) % 56;
            int u = yr / 7, wxr = yr - u * 7;
            int v = xr / 7, wyr = xr - v * 7;
            rowbase[mt * 2 + h] = (size_t)(b * 24) * ROWSTRIDE
                                + (size_t)(u * 8 + v) * (WSZ * 32)
                                + (size_t)(wxr * 7 + wyr) * 32;
        }
    }
#pragma unroll
    for (int nt = 0; nt < 8; ++nt) {
        int jn0 = tile_n + wn0 + nt * 8 + t4 * 2;
        float bias0 = g_b1p[jn0];
        float bias1 = g_b1p[jn0 + 1];
        int g0 = jn0 >> 5, e0 = jn0 & 31;
        size_t coff = (size_t)g0 * ROWSTRIDE + e0;
#pragma unroll
        for (int mt = 0; mt < 4; ++mt) {
            *reinterpret_cast<uint32_t*>(&g_scr[rowbase[mt * 2 + 0] + coff]) =
                packh2(c[mt][nt][0] + bias0, c[mt][nt][1] + bias1);
            *reinterpret_cast<uint32_t*>(&g_scr[rowbase[mt * 2 + 1] + coff]) =
                packh2(c[mt][nt][2] + bias0, c[mt][nt][3] + bias1);
        }
    }
}

// ---------------------------------------------------------------------------
// Stage 3: fp16 attention. 128 threads per (b, head, window), 6 CTAs/SM.
//   V B-fragments via ldmatrix.x4.trans on natural [k][32] layout.
// ---------------------------------------------------------------------------
#define QSTR 40   // halves; frag banks (20*row + t4) % 32 -> conflict-free

__global__ __launch_bounds__(128, 6) void attn_kernel(float* __restrict__ out) {
    __shared__ __half sq[64 * QSTR];
    __shared__ __half sk[56 * QSTR];
    __shared__ __half sv[64 * QSTR];   // V [k=0..63][n=0..31], k>=49 zero

    const int tid = threadIdx.x;
    const int warp = tid >> 5, lane = tid & 31;
    const int tg = lane >> 2, t4 = lane & 3;
    const int bid = blockIdx.x;
    const int b    = bid >> 9;
    const int head = (bid >> 6) & 7;
    const int win  = bid & 63;
    const int u = win >> 3, v = win & 7;
    const int mclass = ((u == 7) ? 2 : 0) + ((v == 7) ? 1 : 0);
    const float* tbl = g_bias + mclass * 3584;

    const __half* base = g_scr + (size_t)(b * 24 + head * 3) * ROWSTRIDE
                               + (size_t)win * (WSZ * 32);

    // q,k,v: 49 rows x 4 16B-units = 196 tasks each
#pragma unroll
    for (int which = 0; which < 3; ++which) {
        const __half* src = base + (size_t)which * ROWSTRIDE;
        __half* dst = (which == 0) ? sq : (which == 1) ? sk : sv;
#pragma unroll
        for (int i = 0; i < 2; ++i) {
            int t = tid + i * 128;
            if (t < 196) {
                int row = t >> 2, o8 = (t & 3) * 8;
                *reinterpret_cast<uint4*>(&dst[row * QSTR + o8]) =
                    *reinterpret_cast<const uint4*>(src + row * 32 + o8);
            }
        }
    }
    // zero pad rows: q rows 49..63, k rows 49..55, v rows 49..63
    for (int t = tid; t < 15 * QSTR; t += 128) sq[49 * QSTR + t] = __ushort_as_half(0);
    for (int t = tid; t < 7 * QSTR; t += 128)  sk[49 * QSTR + t] = __ushort_as_half(0);
    for (int t = tid; t < 15 * QSTR; t += 128) sv[49 * QSTR + t] = __ushort_as_half(0);
    __syncthreads();

    const int r0 = warp * 16 + tg;

    // ---- S = q k^T : cS[8][4], group 7 stays zero (P pad cols) ----
    float cS[8][4];
#pragma unroll
    for (int nt = 0; nt < 8; ++nt)
#pragma unroll
        for (int d = 0; d < 4; ++d) cS[nt][d] = 0.f;
#pragma unroll
    for (int kk = 0; kk < 32; kk += 16) {
        uint32_t a0 = *reinterpret_cast<const uint32_t*>(&sq[r0 * QSTR + kk + 2 * t4]);
        uint32_t a1 = *reinterpret_cast<const uint32_t*>(&sq[(r0 + 8) * QSTR + kk + 2 * t4]);
        uint32_t a2 = *reinterpret_cast<const uint32_t*>(&sq[r0 * QSTR + kk + 2 * t4 + 8]);
        uint32_t a3 = *reinterpret_cast<const uint32_t*>(&sq[(r0 + 8) * QSTR + kk + 2 * t4 + 8]);
#pragma unroll
        for (int nt = 0; nt < 7; ++nt) {
            int n = nt * 8 + tg;
            uint32_t b0 = *reinterpret_cast<const uint32_t*>(&sk[n * QSTR + kk + 2 * t4]);
            uint32_t b1 = *reinterpret_cast<const uint32_t*>(&sk[n * QSTR + kk + 2 * t4 + 8]);
            mma_f16(cS[nt], a0, a1, a2, a3, b0, b1);
        }
    }

    // ---- table-driven scale+bias+mask, in-register softmax ----
    const float SCALE = 0.17677669529663687f;   // 1/sqrt(32)
    const float NEG_INF = __int_as_float(0xff800000u);
#pragma unroll
    for (int r2 = 0; r2 < 2; ++r2) {
        int row = r0 + r2 * 8;
        const float* trow = tbl + row * 56 + 2 * t4;

        float mx = NEG_INF;
#pragma unroll
        for (int nt = 0; nt < 7; ++nt) {
            float2 bv = *reinterpret_cast<const float2*>(trow + nt * 8);
            float v0 = fmaf(cS[nt][r2 * 2 + 0], SCALE, bv.x);
            float v1 = fmaf(cS[nt][r2 * 2 + 1], SCALE, bv.y);
            cS[nt][r2 * 2 + 0] = v0;
            cS[nt][r2 * 2 + 1] = v1;
            mx = fmaxf(mx, fmaxf(v0, v1));
        }
        mx = fmaxf(mx, __shfl_xor_sync(0xffffffffu, mx, 1));
        mx = fmaxf(mx, __shfl_xor_sync(0xffffffffu, mx, 2));
        float sum = 0.f;
#pragma unroll
        for (int nt = 0; nt < 7; ++nt) {
#pragma unroll
            for (int d = 0; d < 2; ++d) {
                float e = __expf(cS[nt][r2 * 2 + d] - mx);
                cS[nt][r2 * 2 + d] = e;
                sum += e;
            }
        }
        sum += __shfl_xor_sync(0xffffffffu, sum, 1);
        sum += __shfl_xor_sync(0xffffffffu, sum, 2);
        float inv = 1.f / sum;
#pragma unroll
        for (int nt = 0; nt < 7; ++nt) {
            cS[nt][r2 * 2 + 0] *= inv;
            cS[nt][r2 * 2 + 1] *= inv;
        }
    }

    // ---- O = P v : A-frags from packed P; B-frags via ldmatrix.x4.trans ----
    float cO[4][4];
#pragma unroll
    for (int nt = 0; nt < 4; ++nt)
#pragma unroll
        for (int d = 0; d < 4; ++d) cO[nt][d] = 0.f;

    // per-lane ldmatrix row address parts: tile = lane/8, row = lane%8
    const int lt = lane >> 3, lr = lane & 7;
    const int k_off = (lt & 1) * 8 + lr;     // within 16-k group
    const int n_off = (lt >> 1) * 8;         // n group 0 or 8
    const uint32_t sv_base = (uint32_t)__cvta_generic_to_shared(sv);

#pragma unroll
    for (int g = 0; g < 4; ++g) {
        uint32_t a0 = packh2(cS[2 * g][0], cS[2 * g][1]);
        uint32_t a1 = packh2(cS[2 * g][2], cS[2 * g][3]);
        uint32_t a2 = packh2(cS[2 * g + 1][0], cS[2 * g + 1][1]);
        uint32_t a3 = packh2(cS[2 * g + 1][2], cS[2 * g + 1][3]);

        uint32_t b00, b01, b10, b11;   // nt 0,1  (n = 0..15)
        ldmx4t(b00, b01, b10, b11,
               sv_base + (uint32_t)(((16 * g + k_off) * QSTR + n_off) * 2));
        uint32_t c00, c01, c10, c11;   // nt 2,3  (n = 16..31)
        ldmx4t(c00, c01, c10, c11,
               sv_base + (uint32_t)(((16 * g + k_off) * QSTR + 16 + n_off) * 2));

        mma_f16(cO[0], a0, a1, a2, a3, b00, b01);
        mma_f16(cO[1], a0, a1, a2, a3, b10, b11);
        mma_f16(cO[2], a0, a1, a2, a3, c00, c01);
        mma_f16(cO[3], a0, a1, a2, a3, c10, c11);
    }

    // ---- store with inverse roll(+3); channel = e*8 + head ----
#pragma unroll
    for (int r2 = 0; r2 < 2; ++r2) {
        int row = r0 + r2 * 8;
        if (row < 49) {
            int qt = (row * 9363) >> 16;
            int ii = row - qt * 7;
            int yo = u * 7 + qt + 3; if (yo >= 56) yo -= 56;
            int xo = v * 7 + ii + 3; if (xo >= 56) xo -= 56;
            float* op = out + ((size_t)((b * 56 + yo) * 56 + xo)) * 256 + head;
#pragma unroll
            for (int nt = 0; nt < 4; ++nt) {
                int e0 = nt * 8 + 2 * t4;
                op[(size_t)e0 * 8]       = cO[nt][r2 * 2 + 0];
                op[(size_t)(e0 + 1) * 8] = cO[nt][r2 * 2 + 1];
            }
        }
    }
}

// ---------------------------------------------------------------------------
extern "C" void kernel_launch(void* const* d_in, const int* in_sizes, int n_in,
                              void* d_out, int out_size) {
    const float* x   = (const float*)d_in[0];
    const float* w1  = (const float*)d_in[1];
    const float* b1  = (const float*)d_in[2];
    const float* pos = (const float*)d_in[3];
    float* out = (float*)d_out;

    static int configured = 0;
    if (!configured) {
        cudaFuncSetAttribute(qkv_gemm_kernel,
                             cudaFuncAttributeMaxDynamicSharedMemorySize,
                             GEMM_SMEM_BYTES);
        configured = 1;
    }

    cvt_x_kernel<<<3136, 256>>>(x);
    permute_w1_kernel<<<768, 256>>>(w1, b1);
    build_bias_kernel<<<56, 256>>>(pos);
    qkv_gemm_kernel<<<dim3(6, 784), 128, GEMM_SMEM_BYTES>>>();
    attn_kernel<<<16384, 128>>>(out);
}

// round 17
// speedup vs baseline: 1.1636x; 1.0218x over previous
#include <cuda_runtime.h>
#include <cuda_fp16.h>
#include <cstdint>

// ---------------------------------------------------------------------------
// ShiftedWindowMSA (B=32, 56x56, EMB=256, 8 heads, 7x7 windows) — fp16 e2e
//  cvt_x:      x -> fp16 g_xh
//  permute_w1: w1 -> g_w1phT [768][256] fp16 K-major, (head,which,e) order
//  build_bias: bias+mask table, 4 window classes x 64 rows x 56 cols
//  qkv_gemm:   fp16 m16n8k16, 128 thr / 4 warps / 64x64 warp tiles, BK=32,
//              3-stage cp.async; fragment loads via ldmatrix.x4 (4x fewer
//              shared-load issues than scalar LDS). Epilogue scatters via
//              roll(-4)+window: q/k/v all [ws][32] fp16, fully vectorized.
//  attn:       fp16 m16n8k16 attention (r16 verbatim); V B-fragments via
//              ldmatrix.x4.trans, table softmax, zero-shuffle P relayout.
// ---------------------------------------------------------------------------

#define WSZ 49
#define ROWSTRIDE 100352   // 64 windows * 49 * 32 per (b,g)

__device__ __half g_scr[(size_t)32 * 24 * ROWSTRIDE];
__device__ __half g_xh[(size_t)32 * 3136 * 256];
__device__ __half g_w1phT[768 * 256];
__device__ float  g_b1p[768];
__device__ float  g_bias[4 * 64 * 56];

__device__ __forceinline__ uint32_t packh2(float lo, float hi) {
    __half2 h = __floats2half2_rn(lo, hi);
    return *reinterpret_cast<uint32_t*>(&h);
}

__device__ __forceinline__ void mma_f16(float c[4], uint32_t a0, uint32_t a1,
                                        uint32_t a2, uint32_t a3,
                                        uint32_t b0, uint32_t b1) {
    asm volatile(
        "mma.sync.aligned.m16n8k16.row.col.f32.f16.f16.f32 "
        "{%0,%1,%2,%3}, {%4,%5,%6,%7}, {%8,%9}, {%0,%1,%2,%3};"
        : "+f"(c[0]), "+f"(c[1]), "+f"(c[2]), "+f"(c[3])
        : "r"(a0), "r"(a1), "r"(a2), "r"(a3), "r"(b0), "r"(b1));
}

__device__ __forceinline__ void ldmx4(uint32_t& r0, uint32_t& r1,
                                      uint32_t& r2, uint32_t& r3,
                                      uint32_t addr) {
    asm volatile(
        "ldmatrix.sync.aligned.m8n8.x4.shared.b16 {%0,%1,%2,%3}, [%4];"
        : "=r"(r0), "=r"(r1), "=r"(r2), "=r"(r3) : "r"(addr));
}

__device__ __forceinline__ void ldmx4t(uint32_t& r0, uint32_t& r1,
                                       uint32_t& r2, uint32_t& r3,
                                       uint32_t addr) {
    asm volatile(
        "ldmatrix.sync.aligned.m8n8.x4.trans.shared.b16 {%0,%1,%2,%3}, [%4];"
        : "=r"(r0), "=r"(r1), "=r"(r2), "=r"(r3) : "r"(addr));
}

// ---------------------------------------------------------------------------
__global__ __launch_bounds__(256) void cvt_x_kernel(const float* __restrict__ x) {
    size_t base = (size_t)blockIdx.x * 1024 + threadIdx.x;
#pragma unroll
    for (int i = 0; i < 4; ++i) {
        size_t g = base + (size_t)i * 256;
        float4 v0 = reinterpret_cast<const float4*>(x)[g * 2];
        float4 v1 = reinterpret_cast<const float4*>(x)[g * 2 + 1];
        uint4 o;
        o.x = packh2(v0.x, v0.y);
        o.y = packh2(v0.z, v0.w);
        o.z = packh2(v1.x, v1.y);
        o.w = packh2(v1.z, v1.w);
        reinterpret_cast<uint4*>(g_xh)[g] = o;
    }
}

__global__ void permute_w1_kernel(const float* __restrict__ w1,
                                  const float* __restrict__ b1) {
    int idx = blockIdx.x * blockDim.x + threadIdx.x;
    if (idx < 768 * 256) {
        int jn = idx >> 8, k = idx & 255;
        int g = jn >> 5, e = jn & 31;
        g_w1phT[idx] = __float2half_rn(w1[k * 768 + e * 24 + g]);
    }
    if (idx < 768) {
        int g = idx >> 5, e = idx & 31;
        g_b1p[idx] = b1[e * 24 + g];
    }
}

__global__ void build_bias_kernel(const float* __restrict__ pos) {
    int idx = blockIdx.x * blockDim.x + threadIdx.x;
    if (idx >= 4 * 64 * 56) return;
    int m = idx / 3584;
    int rem = idx - m * 3584;
    int row = rem / 56, cc = rem - (rem / 56) * 56;
    bool mu = (m >> 1), mv = (m & 1);
    int crow = row < 49 ? row : 48;
    int qt = crow / 7, ii = crow - qt * 7;
    float val = __int_as_float(0xff800000u);
    if (cc < 49) {
        int kt = cc / 7, jj = cc - kt * 7;
        val = pos[(kt - qt + 6) * 13 + (jj - ii + 6)];
        if (mu && ((qt >= 4) != (kt >= 4))) val = __int_as_float(0xff800000u);
        if (mv && ((ii >= 4) != (jj >= 4))) val = __int_as_float(0xff800000u);
    }
    g_bias[idx] = val;
}

// ---------------------------------------------------------------------------
// Stage 2: fp16 QKV GEMM. Block 128x128, 4 warps, warp tile 64x64, BK=32,
//   3-stage cp.async; fragments via ldmatrix.x4.
// ---------------------------------------------------------------------------
#define HSTR 40
#define STAGE_HALVES (2 * 128 * HSTR)
#define GEMM_SMEM_BYTES (3 * STAGE_HALVES * 2)

__global__ __launch_bounds__(128, 2) void qkv_gemm_kernel() {
    extern __shared__ __half smh[];

    const int tid  = threadIdx.x;
    const int warp = tid >> 5, lane = tid & 31;
    const int tg = lane >> 2, t4 = lane & 3;
    const int wm0 = (warp >> 1) * 64;
    const int wn0 = (warp & 1) * 64;
    const int tile_m = blockIdx.y * 128;
    const int tile_n = blockIdx.x * 128;

    const int lrow = tid >> 2;
    const int lunit = (tid & 3) * 8;

    // ldmatrix lane->tile/row decomposition
    const int lt = lane >> 3, lr = lane & 7;
    // A tiles: (m-lo/hi, k-lo/hi):  m_add = (lt&1)*8 + lr, k_add = (lt>>1)*8
    const int a_madd = (lt & 1) * 8 + lr;
    const int a_kadd = (lt >> 1) * 8;
    // B tiles: (k-lo/hi, n-lo/hi):  n_add = (lt>>1)*8 + lr, k_add = (lt&1)*8
    const int b_nadd = (lt >> 1) * 8 + lr;
    const int b_kadd = (lt & 1) * 8;

    auto load_stage = [&](int kc, int s) {
        __half* As = smh + s * STAGE_HALVES;
        __half* Bs = As + 128 * HSTR;
        const __half* asrc = g_xh + (size_t)(tile_m + lrow) * 256 + kc * 32 + lunit;
        const __half* bsrc = g_w1phT + (size_t)(tile_n + lrow) * 256 + kc * 32 + lunit;
#pragma unroll
        for (int j = 0; j < 4; ++j) {
            uint32_t sa = (uint32_t)__cvta_generic_to_shared(
                &As[(lrow + j * 32) * HSTR + lunit]);
            asm volatile("cp.async.cg.shared.global [%0], [%1], 16;"
                         :: "r"(sa), "l"(asrc + (size_t)j * 32 * 256));
        }
#pragma unroll
        for (int j = 0; j < 4; ++j) {
            uint32_t sa = (uint32_t)__cvta_generic_to_shared(
                &Bs[(lrow + j * 32) * HSTR + lunit]);
            asm volatile("cp.async.cg.shared.global [%0], [%1], 16;"
                         :: "r"(sa), "l"(bsrc + (size_t)j * 32 * 256));
        }
        asm volatile("cp.async.commit_group;");
    };

    float c[4][8][4];
#pragma unroll
    for (int a = 0; a < 4; ++a)
#pragma unroll
        for (int b = 0; b < 8; ++b)
#pragma unroll
            for (int d = 0; d < 4; ++d) c[a][b][d] = 0.f;

    load_stage(0, 0);
    load_stage(1, 1);

#pragma unroll 1
    for (int kc = 0; kc < 8; ++kc) {
        if (kc < 7) asm volatile("cp.async.wait_group 1;");
        else        asm volatile("cp.async.wait_group 0;");
        __syncthreads();
        if (kc + 2 < 8) load_stage(kc + 2, (kc + 2) % 3);

        const __half* aa = smh + (kc % 3) * STAGE_HALVES;
        const __half* bb = aa + 128 * HSTR;
        uint32_t aabase = (uint32_t)__cvta_generic_to_shared(aa);
        uint32_t bbbase = (uint32_t)__cvta_generic_to_shared(bb);
#pragma unroll
        for (int kk = 0; kk < 32; kk += 16) {
            uint32_t a[4][4];
#pragma unroll
            for (int mt = 0; mt < 4; ++mt) {
                int m_row = wm0 + mt * 16 + a_madd;
                ldmx4(a[mt][0], a[mt][1], a[mt][2], a[mt][3],
                      aabase + (uint32_t)((m_row * HSTR + kk + a_kadd) * 2));
            }
            uint32_t bf[8][2];
#pragma unroll
            for (int np = 0; np < 4; ++np) {
                int n_row = wn0 + np * 16 + b_nadd;
                ldmx4(bf[2 * np][0], bf[2 * np][1],
                      bf[2 * np + 1][0], bf[2 * np + 1][1],
                      bbbase + (uint32_t)((n_row * HSTR + kk + b_kadd) * 2));
            }
#pragma unroll
            for (int nt = 0; nt < 8; ++nt)
#pragma unroll
                for (int mt = 0; mt < 4; ++mt)
                    mma_f16(c[mt][nt], a[mt][0], a[mt][1], a[mt][2], a[mt][3],
                            bf[nt][0], bf[nt][1]);
        }
    }

    // epilogue: scatter via roll(-4)+window partition; fp16(acc+bias)
    size_t rowbase[8];
#pragma unroll
    for (int mt = 0; mt < 4; ++mt) {
#pragma unroll
        for (int h = 0; h < 2; ++h) {
            int n = tile_m + wm0 + mt * 16 + tg + h * 8;
            int b = n / 3136;
            int r = n - b * 3136;
            int y = r / 56, xx = r - y * 56;
            int yr = (y + 52) % 56;
            int xr = (xx + 52) % 56;
            int u = yr / 7, wxr = yr - u * 7;
            int v = xr / 7, wyr = xr - v * 7;
            rowbase[mt * 2 + h] = (size_t)(b * 24) * ROWSTRIDE
                                + (size_t)(u * 8 + v) * (WSZ * 32)
                                + (size_t)(wxr * 7 + wyr) * 32;
        }
    }
#pragma unroll
    for (int nt = 0; nt < 8; ++nt) {
        int jn0 = tile_n + wn0 + nt * 8 + t4 * 2;
        float bias0 = g_b1p[jn0];
        float bias1 = g_b1p[jn0 + 1];
        int g0 = jn0 >> 5, e0 = jn0 & 31;
        size_t coff = (size_t)g0 * ROWSTRIDE + e0;
#pragma unroll
        for (int mt = 0; mt < 4; ++mt) {
            *reinterpret_cast<uint32_t*>(&g_scr[rowbase[mt * 2 + 0] + coff]) =
                packh2(c[mt][nt][0] + bias0, c[mt][nt][1] + bias1);
            *reinterpret_cast<uint32_t*>(&g_scr[rowbase[mt * 2 + 1] + coff]) =
                packh2(c[mt][nt][2] + bias0, c[mt][nt][3] + bias1);
        }
    }
}

// ---------------------------------------------------------------------------
// Stage 3: fp16 attention (r16 verbatim). 128 threads per (b, head, window).
// ---------------------------------------------------------------------------
#define QSTR 40   // halves; frag banks (20*row + t4) % 32 -> conflict-free

__global__ __launch_bounds__(128, 6) void attn_kernel(float* __restrict__ out) {
    __shared__ __half sq[64 * QSTR];
    __shared__ __half sk[56 * QSTR];
    __shared__ __half sv[64 * QSTR];   // V [k=0..63][n=0..31], k>=49 zero

    const int tid = threadIdx.x;
    const int warp = tid >> 5, lane = tid & 31;
    const int tg = lane >> 2, t4 = lane & 3;
    const int bid = blockIdx.x;
    const int b    = bid >> 9;
    const int head = (bid >> 6) & 7;
    const int win  = bid & 63;
    const int u = win >> 3, v = win & 7;
    const int mclass = ((u == 7) ? 2 : 0) + ((v == 7) ? 1 : 0);
    const float* tbl = g_bias + mclass * 3584;

    const __half* base = g_scr + (size_t)(b * 24 + head * 3) * ROWSTRIDE
                               + (size_t)win * (WSZ * 32);

    // q,k,v: 49 rows x 4 16B-units = 196 tasks each
#pragma unroll
    for (int which = 0; which < 3; ++which) {
        const __half* src = base + (size_t)which * ROWSTRIDE;
        __half* dst = (which == 0) ? sq : (which == 1) ? sk : sv;
#pragma unroll
        for (int i = 0; i < 2; ++i) {
            int t = tid + i * 128;
            if (t < 196) {
                int row = t >> 2, o8 = (t & 3) * 8;
                *reinterpret_cast<uint4*>(&dst[row * QSTR + o8]) =
                    *reinterpret_cast<const uint4*>(src + row * 32 + o8);
            }
        }
    }
    // zero pad rows
    for (int t = tid; t < 15 * QSTR; t += 128) sq[49 * QSTR + t] = __ushort_as_half(0);
    for (int t = tid; t < 7 * QSTR; t += 128)  sk[49 * QSTR + t] = __ushort_as_half(0);
    for (int t = tid; t < 15 * QSTR; t += 128) sv[49 * QSTR + t] = __ushort_as_half(0);
    __syncthreads();

    const int r0 = warp * 16 + tg;

    // ---- S = q k^T : cS[8][4], group 7 stays zero (P pad cols) ----
    float cS[8][4];
#pragma unroll
    for (int nt = 0; nt < 8; ++nt)
#pragma unroll
        for (int d = 0; d < 4; ++d) cS[nt][d] = 0.f;
#pragma unroll
    for (int kk = 0; kk < 32; kk += 16) {
        uint32_t a0 = *reinterpret_cast<const uint32_t*>(&sq[r0 * QSTR + kk + 2 * t4]);
        uint32_t a1 = *reinterpret_cast<const uint32_t*>(&sq[(r0 + 8) * QSTR + kk + 2 * t4]);
        uint32_t a2 = *reinterpret_cast<const uint32_t*>(&sq[r0 * QSTR + kk + 2 * t4 + 8]);
        uint32_t a3 = *reinterpret_cast<const uint32_t*>(&sq[(r0 + 8) * QSTR + kk + 2 * t4 + 8]);
#pragma unroll
        for (int nt = 0; nt < 7; ++nt) {
            int n = nt * 8 + tg;
            uint32_t b0 = *reinterpret_cast<const uint32_t*>(&sk[n * QSTR + kk + 2 * t4]);
            uint32_t b1 = *reinterpret_cast<const uint32_t*>(&sk[n * QSTR + kk + 2 * t4 + 8]);
            mma_f16(cS[nt], a0, a1, a2, a3, b0, b1);
        }
    }

    // ---- table-driven scale+bias+mask, in-register softmax ----
    const float SCALE = 0.17677669529663687f;   // 1/sqrt(32)
    const float NEG_INF = __int_as_float(0xff800000u);
#pragma unroll
    for (int r2 = 0; r2 < 2; ++r2) {
        int row = r0 + r2 * 8;
        const float* trow = tbl + row * 56 + 2 * t4;

        float mx = NEG_INF;
#pragma unroll
        for (int nt = 0; nt < 7; ++nt) {
            float2 bv = *reinterpret_cast<const float2*>(trow + nt * 8);
            float v0 = fmaf(cS[nt][r2 * 2 + 0], SCALE, bv.x);
            float v1 = fmaf(cS[nt][r2 * 2 + 1], SCALE, bv.y);
            cS[nt][r2 * 2 + 0] = v0;
            cS[nt][r2 * 2 + 1] = v1;
            mx = fmaxf(mx, fmaxf(v0, v1));
        }
        mx = fmaxf(mx, __shfl_xor_sync(0xffffffffu, mx, 1));
        mx = fmaxf(mx, __shfl_xor_sync(0xffffffffu, mx, 2));
        float sum = 0.f;
#pragma unroll
        for (int nt = 0; nt < 7; ++nt) {
#pragma unroll
            for (int d = 0; d < 2; ++d) {
                float e = __expf(cS[nt][r2 * 2 + d] - mx);
                cS[nt][r2 * 2 + d] = e;
                sum += e;
            }
        }
        sum += __shfl_xor_sync(0xffffffffu, sum, 1);
        sum += __shfl_xor_sync(0xffffffffu, sum, 2);
        float inv = 1.f / sum;
#pragma unroll
        for (int nt = 0; nt < 7; ++nt) {
            cS[nt][r2 * 2 + 0] *= inv;
            cS[nt][r2 * 2 + 1] *= inv;
        }
    }

    // ---- O = P v : A-frags from packed P; B-frags via ldmatrix.x4.trans ----
    float cO[4][4];
#pragma unroll
    for (int nt = 0; nt < 4; ++nt)
#pragma unroll
        for (int d = 0; d < 4; ++d) cO[nt][d] = 0.f;

    const int lt = lane >> 3, lr = lane & 7;
    const int k_off = (lt & 1) * 8 + lr;
    const int n_off = (lt >> 1) * 8;
    const uint32_t sv_base = (uint32_t)__cvta_generic_to_shared(sv);

#pragma unroll
    for (int g = 0; g < 4; ++g) {
        uint32_t a0 = packh2(cS[2 * g][0], cS[2 * g][1]);
        uint32_t a1 = packh2(cS[2 * g][2], cS[2 * g][3]);
        uint32_t a2 = packh2(cS[2 * g + 1][0], cS[2 * g + 1][1]);
        uint32_t a3 = packh2(cS[2 * g + 1][2], cS[2 * g + 1][3]);

        uint32_t b00, b01, b10, b11;
        ldmx4t(b00, b01, b10, b11,
               sv_base + (uint32_t)(((16 * g + k_off) * QSTR + n_off) * 2));
        uint32_t c00, c01, c10, c11;
        ldmx4t(c00, c01, c10, c11,
               sv_base + (uint32_t)(((16 * g + k_off) * QSTR + 16 + n_off) * 2));

        mma_f16(cO[0], a0, a1, a2, a3, b00, b01);
        mma_f16(cO[1], a0, a1, a2, a3, b10, b11);
        mma_f16(cO[2], a0, a1, a2, a3, c00, c01);
        mma_f16(cO[3], a0, a1, a2, a3, c10, c11);
    }

    // ---- store with inverse roll(+3); channel = e*8 + head ----
#pragma unroll
    for (int r2 = 0; r2 < 2; ++r2) {
        int row = r0 + r2 * 8;
        if (row < 49) {
            int qt = (row * 9363) >> 16;
            int ii = row - qt * 7;
            int yo = u * 7 + qt + 3; if (yo >= 56) yo -= 56;
            int xo = v * 7 + ii + 3; if (xo >= 56) xo -= 56;
            float* op = out + ((size_t)((b * 56 + yo) * 56 + xo)) * 256 + head;
#pragma unroll
            for (int nt = 0; nt < 4; ++nt) {
                int e0 = nt * 8 + 2 * t4;
                op[(size_t)e0 * 8]       = cO[nt][r2 * 2 + 0];
                op[(size_t)(e0 + 1) * 8] = cO[nt][r2 * 2 + 1];
            }
        }
    }
}

// ---------------------------------------------------------------------------
extern "C" void kernel_launch(void* const* d_in, const int* in_sizes, int n_in,
                              void* d_out, int out_size) {
    const float* x   = (const float*)d_in[0];
    const float* w1  = (const float*)d_in[1];
    const float* b1  = (const float*)d_in[2];
    const float* pos = (const float*)d_in[3];
    float* out = (float*)d_out;

    static int configured = 0;
    if (!configured) {
        cudaFuncSetAttribute(qkv_gemm_kernel,
                             cudaFuncAttributeMaxDynamicSharedMemorySize,
                             GEMM_SMEM_BYTES);
        configured = 1;
    }

    cvt_x_kernel<<<3136, 256>>>(x);
    permute_w1_kernel<<<768, 256>>>(w1, b1);
    build_bias_kernel<<<56, 256>>>(pos);
    qkv_gemm_kernel<<<dim3(6, 784), 128, GEMM_SMEM_BYTES>>>();
    attn_kernel<<<16384, 128>>>(out);
}